// round 1
// baseline (speedup 1.0000x reference)
#include <cuda_runtime.h>
#include <cstdint>
#include <cstddef>

// Problem dims
#define S 512   // sentences
#define N 256   // doc tokens per sentence
#define Q 512   // query rows
#define F 50    // features
#define FP 52   // padded feature stride (16B-aligned float4 rows)

// Global scratch (no allocations allowed -> __device__ globals)
__device__ __align__(16) float g_E[(size_t)S * N * Q];   // exp(sXY) per sentence
__device__ __align__(16) float g_qw3T[F * Q];            // [k][q] = query[q][k]*w3[k]*LOG2E
__device__ __align__(16) float g_qpad[Q * FP];           // query rows padded to 52
__device__ __align__(16) float g_b[Q];                   // (query@w2)*LOG2E

// Fast exp2 on the FMA pipe (avoids MUFU bottleneck). |err| ~1e-7.
__device__ __forceinline__ float fexp2(float x) {
    x = fminf(fmaxf(x, -126.f), 126.f);
    float t = x + 12582912.f;                 // 1.5*2^23 : round-to-nearest-int trick
    int   n = __float_as_int(t) - 0x4B400000; // integer part
    float f = x - (t - 12582912.f);           // frac in [-0.5, 0.5]
    float y = f * 0.6931471805599453f;        // f*ln2
    float p = 1.3888889e-3f;
    p = fmaf(p, y, 8.3333338e-3f);
    p = fmaf(p, y, 4.1666668e-2f);
    p = fmaf(p, y, 1.6666667e-1f);
    p = fmaf(p, y, 0.5f);
    p = fmaf(p, y, 1.0f);
    p = fmaf(p, y, 1.0f);
    return p * __int_as_float((n + 127) << 23);
}

// acc[0..51] += w * p[0..51], float4 loads
__device__ __forceinline__ void axpy52(float w, const float* __restrict__ p, float* acc) {
#pragma unroll
    for (int q = 0; q < 13; q++) {
        float4 v = ((const float4*)p)[q];
        acc[4*q+0] = fmaf(w, v.x, acc[4*q+0]);
        acc[4*q+1] = fmaf(w, v.y, acc[4*q+1]);
        acc[4*q+2] = fmaf(w, v.z, acc[4*q+2]);
        acc[4*q+3] = fmaf(w, v.w, acc[4*q+3]);
    }
}

__global__ void prep_kernel(const float* __restrict__ query, const float* __restrict__ W) {
    int q = blockIdx.x * blockDim.x + threadIdx.x;
    if (q >= Q) return;
    const float LOG2E = 1.4426950408889634f;
    float qv[F];
    float b = 0.f;
#pragma unroll
    for (int k = 0; k < F; k++) {
        qv[k] = query[q * F + k];
        b = fmaf(qv[k], W[F + k], b);
    }
    g_b[q] = b * LOG2E;
#pragma unroll
    for (int k = 0; k < F; k++) g_qw3T[k * Q + q] = qv[k] * W[2 * F + k] * LOG2E;
#pragma unroll
    for (int k = 0; k < FP; k++) g_qpad[q * FP + k] = (k < F) ? qv[k] : 0.f;
}

__global__ void __launch_bounds__(512, 1)
cross_kernel(const float* __restrict__ doc, const float* __restrict__ W,
             float* __restrict__ out) {
    extern __shared__ float sm[];
    float* sen     = sm;                    // N*FP   (13312)
    float* tsh     = sen + N * FP;          // Q*FP   (26624)
    float* ad2q    = tsh + Q * FP;          // N*FP   (13312)
    float* a_sc    = ad2q + N * FP;         // N
    float* rsum    = a_sc + N;              // N  -> becomes 1/rsum
    float* invcsum = rsum + N;              // Q
    float* w1sh    = invcsum + Q;           // FP

    const int s   = blockIdx.x;
    const int tid = threadIdx.x;
    const float LOG2E = 1.4426950408889634f;

    // ---- load sentence tile (padded), init reductions ----
    const float* dsen = doc + (size_t)s * N * F;
    for (int idx = tid; idx < N * FP; idx += 512) {
        int i = idx / FP, k = idx - i * FP;
        sen[idx] = (k < F) ? dsen[i * F + k] : 0.f;
    }
    if (tid < N)  rsum[tid] = 0.f;
    if (tid < FP) w1sh[tid] = (tid < F) ? W[tid] * LOG2E : 0.f;
    __syncthreads();

    // ---- a_sc[i] = (sen_i . w1) * LOG2E ----
    if (tid < N) {
        const float* sr = sen + tid * FP;
        float a0 = 0.f, a1 = 0.f, a2 = 0.f, a3 = 0.f;
#pragma unroll
        for (int k = 0; k < FP; k += 4) {
            a0 = fmaf(sr[k + 0], w1sh[k + 0], a0);
            a1 = fmaf(sr[k + 1], w1sh[k + 1], a1);
            a2 = fmaf(sr[k + 2], w1sh[k + 2], a2);
            a3 = fmaf(sr[k + 3], w1sh[k + 3], a3);
        }
        a_sc[tid] = (a0 + a1) + (a2 + a3);
    }
    __syncthreads();

    // ---- Phase B (column-owned, thread = query j):
    //      E = exp(sXY), column sums (csum), row sums (rsum via warp reduce + smem atomics)
    {
        const int j = tid;
        float qw[FP];
#pragma unroll
        for (int k = 0; k < FP; k++) qw[k] = (k < F) ? g_qw3T[k * Q + j] : 0.f;
        const float bj = g_b[j];
        float csum = 0.f;
        float* Ecol = g_E + (size_t)s * N * Q + j;
        for (int i = 0; i < N; i++) {
            const float4* sp = (const float4*)(sen + i * FP);
            float m0 = 0.f, m1 = 0.f, m2 = 0.f, m3 = 0.f;
#pragma unroll
            for (int q4 = 0; q4 < 13; q4++) {
                float4 v = sp[q4];
                m0 = fmaf(v.x, qw[4 * q4 + 0], m0);
                m1 = fmaf(v.y, qw[4 * q4 + 1], m1);
                m2 = fmaf(v.z, qw[4 * q4 + 2], m2);
                m3 = fmaf(v.w, qw[4 * q4 + 3], m3);
            }
            float e = fexp2(a_sc[i] + bj + ((m0 + m1) + (m2 + m3)));
            Ecol[(size_t)i * Q] = e;
            csum += e;
            float v = e;
#pragma unroll
            for (int off = 16; off; off >>= 1) v += __shfl_xor_sync(0xffffffffu, v, off);
            if ((tid & 31) == 0) atomicAdd(&rsum[i], v);
        }
        invcsum[j] = 1.0f / csum;
    }
    __syncthreads();
    if (tid < N) rsum[tid] = 1.0f / rsum[tid];   // invrsum
    __syncthreads();

    // ---- Phase C (column-owned): t_j = sum_i (E_ij / rsum_i) * sen_i ----
    {
        const int j = tid;
        float tacc[FP];
#pragma unroll
        for (int k = 0; k < FP; k++) tacc[k] = 0.f;
        const float* Ecol = g_E + (size_t)s * N * Q + j;
        for (int i = 0; i < N; i++) {
            float w = Ecol[(size_t)i * Q] * rsum[i];
            axpy52(w, sen + i * FP, tacc);
        }
#pragma unroll
        for (int k = 0; k < FP; k++) tsh[j * FP + k] = tacc[k];
    }
    __syncthreads();

    // ---- Phase D (row-owned pairs): thread pair (2i, 2i+1) splits j-range ----
    const int i  = tid >> 1;
    const int h  = tid & 1;
    const int jb = h * (Q / 2);
    const float* Erow = g_E + ((size_t)s * N + i) * Q + jb;
    float* orow = out + ((size_t)s * N + i) * 200;

    // D1: aD2Q = sum_j (E_ij / csum_j) * query_j
    {
        float acc[FP];
#pragma unroll
        for (int k = 0; k < FP; k++) acc[k] = 0.f;
        for (int jj = 0; jj < Q / 2; jj += 4) {
            float4 e4 = *(const float4*)(Erow + jj);
            axpy52(e4.x * invcsum[jb + jj + 0], g_qpad + (jb + jj + 0) * FP, acc);
            axpy52(e4.y * invcsum[jb + jj + 1], g_qpad + (jb + jj + 1) * FP, acc);
            axpy52(e4.z * invcsum[jb + jj + 2], g_qpad + (jb + jj + 2) * FP, acc);
            axpy52(e4.w * invcsum[jb + jj + 3], g_qpad + (jb + jj + 3) * FP, acc);
        }
#pragma unroll
        for (int k = 0; k < F; k++) acc[k] += __shfl_xor_sync(0xffffffffu, acc[k], 1);
        if (h == 0) {
#pragma unroll
            for (int k = 0; k < F; k++) {
                orow[50 + k]     = acc[k];
                ad2q[i * FP + k] = acc[k];
            }
        }
    }

    // D2: aQ2D = sum_j (E_ij / csum_j) * t_j ; then write remaining output fields
    {
        float acc[FP];
#pragma unroll
        for (int k = 0; k < FP; k++) acc[k] = 0.f;
        for (int jj = 0; jj < Q / 2; jj += 4) {
            float4 e4 = *(const float4*)(Erow + jj);
            axpy52(e4.x * invcsum[jb + jj + 0], tsh + (jb + jj + 0) * FP, acc);
            axpy52(e4.y * invcsum[jb + jj + 1], tsh + (jb + jj + 1) * FP, acc);
            axpy52(e4.z * invcsum[jb + jj + 2], tsh + (jb + jj + 2) * FP, acc);
            axpy52(e4.w * invcsum[jb + jj + 3], tsh + (jb + jj + 3) * FP, acc);
        }
#pragma unroll
        for (int k = 0; k < F; k++) acc[k] += __shfl_xor_sync(0xffffffffu, acc[k], 1);
        const float* sr = sen + i * FP;
        if (h == 0) {
#pragma unroll
            for (int k = 0; k < F; k++) {
                float sv = sr[k];
                orow[k]       = sv;                        // sen
                orow[100 + k] = sv * ad2q[i * FP + k];     // sen * aD2Q
            }
        } else {
#pragma unroll
            for (int k = 0; k < F; k++) {
                orow[150 + k] = sr[k] * acc[k];            // sen * aQ2D
            }
        }
    }
}

extern "C" void kernel_launch(void* const* d_in, const int* in_sizes, int n_in,
                              void* d_out, int out_size) {
    const float* query = (const float*)d_in[0];  // [512,50]
    const float* doc   = (const float*)d_in[1];  // [512,256,50]
    const float* W     = (const float*)d_in[2];  // [150]
    float* out = (float*)d_out;                  // [512,256,200] fp32
    (void)in_sizes; (void)n_in; (void)out_size;

    const size_t smem_bytes =
        (size_t)(N * FP + Q * FP + N * FP + N + N + Q + FP) * sizeof(float); // 217296 B
    cudaFuncSetAttribute(cross_kernel, cudaFuncAttributeMaxDynamicSharedMemorySize,
                         (int)smem_bytes);

    prep_kernel<<<2, 256>>>(query, W);
    cross_kernel<<<S, 512, smem_bytes>>>(doc, W, out);
}

// round 4
// speedup vs baseline: 1.2148x; 1.2148x over previous
#include <cuda_runtime.h>
#include <cstdint>
#include <cstddef>

// Problem dims
#define S 512   // sentences
#define N 256   // doc tokens per sentence
#define Q 512   // query rows
#define F 50    // features
#define FP 52   // sen stride (16B-aligned float4 rows)
#define FQ 56   // qpad/tsh stride (split 28/28 for feature-split phase D)

#define GRID 148  // persistent CTAs

// Global scratch (no allocations allowed -> __device__ globals)
__device__ __align__(16) float g_E[(size_t)S * N * Q];   // exp(sXY) per sentence
__device__ __align__(16) float g_qw3T[F * Q];            // [k][q] = query[q][k]*w3[k]*LOG2E
__device__ __align__(16) float g_qpad[Q * FQ];           // query rows padded to 56
__device__ __align__(16) float g_b[Q];                   // (query@w2)*LOG2E

// Fast exp2 on the FMA pipe (avoids MUFU bottleneck). |err| ~1e-7.
__device__ __forceinline__ float fexp2(float x) {
    x = fminf(fmaxf(x, -126.f), 126.f);
    float t = x + 12582912.f;                 // 1.5*2^23 round-to-nearest-int trick
    int   n = __float_as_int(t) - 0x4B400000;
    float f = x - (t - 12582912.f);
    float y = f * 0.6931471805599453f;
    float p = 1.3888889e-3f;
    p = fmaf(p, y, 8.3333338e-3f);
    p = fmaf(p, y, 4.1666668e-2f);
    p = fmaf(p, y, 1.6666667e-1f);
    p = fmaf(p, y, 0.5f);
    p = fmaf(p, y, 1.0f);
    p = fmaf(p, y, 1.0f);
    return p * __int_as_float((n + 127) << 23);
}

// acc[0..51] += w * p[0..51], float4 loads
__device__ __forceinline__ void axpy52(float w, const float* __restrict__ p, float* acc) {
#pragma unroll
    for (int q = 0; q < 13; q++) {
        float4 v = ((const float4*)p)[q];
        acc[4*q+0] = fmaf(w, v.x, acc[4*q+0]);
        acc[4*q+1] = fmaf(w, v.y, acc[4*q+1]);
        acc[4*q+2] = fmaf(w, v.z, acc[4*q+2]);
        acc[4*q+3] = fmaf(w, v.w, acc[4*q+3]);
    }
}

// acc[0..27] += w * p[0..27], float4 loads (feature-split phase D)
__device__ __forceinline__ void axpy28(float w, const float* __restrict__ p, float* acc) {
#pragma unroll
    for (int q = 0; q < 7; q++) {
        float4 v = ((const float4*)p)[q];
        acc[4*q+0] = fmaf(w, v.x, acc[4*q+0]);
        acc[4*q+1] = fmaf(w, v.y, acc[4*q+1]);
        acc[4*q+2] = fmaf(w, v.z, acc[4*q+2]);
        acc[4*q+3] = fmaf(w, v.w, acc[4*q+3]);
    }
}

__global__ void prep_kernel(const float* __restrict__ query, const float* __restrict__ W) {
    int q = blockIdx.x * blockDim.x + threadIdx.x;
    if (q >= Q) return;
    const float LOG2E = 1.4426950408889634f;
    float qv[F];
    float b = 0.f;
#pragma unroll
    for (int k = 0; k < F; k++) {
        qv[k] = query[q * F + k];
        b = fmaf(qv[k], W[F + k], b);
    }
    g_b[q] = b * LOG2E;
#pragma unroll
    for (int k = 0; k < F; k++) g_qw3T[k * Q + q] = qv[k] * W[2 * F + k] * LOG2E;
#pragma unroll
    for (int k = 0; k < FQ; k++) g_qpad[q * FQ + k] = (k < F) ? qv[k] : 0.f;
}

__global__ void __launch_bounds__(512, 1)
cross_kernel(const float* __restrict__ doc, const float* __restrict__ W,
             float* __restrict__ out) {
    extern __shared__ float sm[];
    float* sen     = sm;                    // N*FP  = 13312 floats
    float* tsh     = sen + N * FP;          // Q*FQ  = 28672 floats
    float* a_sc    = tsh + Q * FQ;          // N
    float* rsum    = a_sc + N;              // N  -> becomes 1/rsum
    float* invcsum = rsum + N;              // Q
    float* w1sh    = invcsum + Q;           // FP

    const int tid = threadIdx.x;
    const float LOG2E = 1.4426950408889634f;

    const float bj = g_b[tid];

    if (tid < FP) w1sh[tid] = (tid < F) ? W[tid] * LOG2E : 0.f;

    for (int s = blockIdx.x; s < S; s += GRID) {
        __syncthreads();   // guard smem reuse against previous iteration's readers

        // ---- load sentence tile (padded), init reductions ----
        const float* dsen = doc + (size_t)s * N * F;
        for (int idx = tid; idx < N * FP; idx += 512) {
            int i = idx / FP, k = idx - i * FP;
            sen[idx] = (k < F) ? dsen[i * F + k] : 0.f;
        }
        if (tid < N) rsum[tid] = 0.f;
        __syncthreads();

        // ---- a_sc[i] = (sen_i . w1) * LOG2E ----
        if (tid < N) {
            const float* sr = sen + tid * FP;
            float a0 = 0.f, a1 = 0.f, a2 = 0.f, a3 = 0.f;
#pragma unroll
            for (int k = 0; k < FP; k += 4) {
                a0 = fmaf(sr[k + 0], w1sh[k + 0], a0);
                a1 = fmaf(sr[k + 1], w1sh[k + 1], a1);
                a2 = fmaf(sr[k + 2], w1sh[k + 2], a2);
                a3 = fmaf(sr[k + 3], w1sh[k + 3], a3);
            }
            a_sc[tid] = (a0 + a1) + (a2 + a3);
        }
        __syncthreads();

        // ---- Phase B (thread = query j): E = exp(sXY), csum, rsum ----
        // qw loaded here (not hoisted) so its 52 regs die before Phases C/D.
        {
            const int j = tid;
            float qw[FP];
#pragma unroll
            for (int k = 0; k < F; k++) qw[k] = g_qw3T[k * Q + j];
#pragma unroll
            for (int k = F; k < FP; k++) qw[k] = 0.f;

            float csum = 0.f;
            float* Ecol = g_E + (size_t)s * N * Q + j;
            for (int i = 0; i < N; i++) {
                const float4* sp = (const float4*)(sen + i * FP);
                float m0 = 0.f, m1 = 0.f, m2 = 0.f, m3 = 0.f;
#pragma unroll
                for (int q4 = 0; q4 < 13; q4++) {
                    float4 v = sp[q4];
                    m0 = fmaf(v.x, qw[4 * q4 + 0], m0);
                    m1 = fmaf(v.y, qw[4 * q4 + 1], m1);
                    m2 = fmaf(v.z, qw[4 * q4 + 2], m2);
                    m3 = fmaf(v.w, qw[4 * q4 + 3], m3);
                }
                float e = fexp2(a_sc[i] + bj + ((m0 + m1) + (m2 + m3)));
                Ecol[(size_t)i * Q] = e;
                csum += e;
                float v = e;
#pragma unroll
                for (int off = 16; off; off >>= 1) v += __shfl_xor_sync(0xffffffffu, v, off);
                if ((tid & 31) == 0) atomicAdd(&rsum[i], v);
            }
            invcsum[j] = 1.0f / csum;
        }
        __syncthreads();
        if (tid < N) rsum[tid] = 1.0f / rsum[tid];   // invrsum
        __syncthreads();

        // ---- Phase C (thread = query j): t_j = sum_i (E_ij * invrsum_i) * sen_i ----
        {
            const int j = tid;
            float tacc[FP];
#pragma unroll
            for (int k = 0; k < FP; k++) tacc[k] = 0.f;
            const float* Ecol = g_E + (size_t)s * N * Q + j;
            for (int i = 0; i < N; i++) {
                float w = Ecol[(size_t)i * Q] * rsum[i];
                axpy52(w, sen + i * FP, tacc);
            }
            float* tr = tsh + j * FQ;
#pragma unroll
            for (int k = 0; k < FP; k++) tr[k] = tacc[k];
#pragma unroll
            for (int k = FP; k < FQ; k++) tr[k] = 0.f;
        }
        __syncthreads();

        // ---- Phase D (fused D1+D2, feature-split): thread pair (2i,2i+1)
        //      owns features [h*28, h*28+28) of row i; loops all 512 j.
        //      One E load + one weight feeds both accumulators.
        {
            const int i  = tid >> 1;
            const int h  = tid & 1;
            const int ko = h * 28;
            const float* Erow = g_E + ((size_t)s * N + i) * Q;

            float acc1[28], acc2[28];
#pragma unroll
            for (int k = 0; k < 28; k++) { acc1[k] = 0.f; acc2[k] = 0.f; }

            for (int jj = 0; jj < Q; jj += 4) {
                float4 e4 = *(const float4*)(Erow + jj);
                float4 ic = *(const float4*)(invcsum + jj);
                float w0 = e4.x * ic.x, w1 = e4.y * ic.y;
                float w2 = e4.z * ic.z, w3 = e4.w * ic.w;
                const float* qp = g_qpad + (size_t)jj * FQ + ko;
                const float* tp = tsh + jj * FQ + ko;
                axpy28(w0, qp,          acc1);  axpy28(w0, tp,          acc2);
                axpy28(w1, qp + FQ,     acc1);  axpy28(w1, tp + FQ,     acc2);
                axpy28(w2, qp + 2*FQ,   acc1);  axpy28(w2, tp + 2*FQ,   acc2);
                axpy28(w3, qp + 3*FQ,   acc1);  axpy28(w3, tp + 3*FQ,   acc2);
            }

            // write output: this thread owns features ko..ko+27 (clipped to 50)
            float* orow = out + ((size_t)s * N + i) * 200;
            const float* sr = sen + i * FP;
#pragma unroll
            for (int k = 0; k < 28; k++) {
                int kg = ko + k;
                if (kg < F) {
                    float sv = sr[kg];
                    orow[kg]       = sv;              // sen
                    orow[50 + kg]  = acc1[k];         // aD2Q
                    orow[100 + kg] = sv * acc1[k];    // sen * aD2Q
                    orow[150 + kg] = sv * acc2[k];    // sen * aQ2D
                }
            }
        }
    }
}

extern "C" void kernel_launch(void* const* d_in, const int* in_sizes, int n_in,
                              void* d_out, int out_size) {
    const float* query = (const float*)d_in[0];  // [512,50]
    const float* doc   = (const float*)d_in[1];  // [512,256,50]
    const float* W     = (const float*)d_in[2];  // [150]
    float* out = (float*)d_out;                  // [512,256,200] fp32
    (void)in_sizes; (void)n_in; (void)out_size;

    const size_t smem_bytes =
        (size_t)(N * FP + Q * FQ + N + N + Q + FP) * sizeof(float); // 172,240 B
    cudaFuncSetAttribute(cross_kernel, cudaFuncAttributeMaxDynamicSharedMemorySize,
                         (int)smem_bytes);

    prep_kernel<<<2, 256>>>(query, W);
    cross_kernel<<<GRID, 512, smem_bytes>>>(doc, W, out);
}